// round 15
// baseline (speedup 1.0000x reference)
#include <cuda_runtime.h>
#include <cuda_bf16.h>
#include <math.h>

#define CN (256*1024)

// ---------------- device scratch ----------------
__device__ float g_x[2*256*1024];     // LN1 out, (B,C,N)
__device__ float g_q[2*256*1024];     // q proj (B,C,N)
__device__ float g_vgrid[16*64*2];    // normalized kv coords per (b,g)
__device__ unsigned short g_fx[16*2048];  // bf16 CPB fx per (bh, ii, j)
__device__ unsigned short g_fy[16*2048];  // bf16 CPB fy per (bh, py, j)
__device__ unsigned g_w1v[2048];      // pre-packed W1 B-fragments (per-lane bf16x2)
__device__ float g_k[2*256*64];
__device__ float g_v[2*256*64];
__device__ unsigned g_attn[2048*128]; // attention out, bf16x2 packed [row][c/2]
__device__ float g_srcp[2*1024*256];  // src + out proj (fp32)
__device__ unsigned g_src2[2048*128]; // LN2 out, bf16x2 packed
__device__ unsigned g_ffnh[2048*512]; // ffn hidden, bf16x2 packed
__device__ unsigned g_wp[294912];     // packed weights: wout[32768] | ffn_w1T[131072] | ffn_w2T[131072]

__device__ __forceinline__ unsigned pack_bf16(float lo, float hi) {
    __nv_bfloat162 v = __floats2bfloat162_rn(lo, hi);
    return *(unsigned*)&v;
}

__device__ __forceinline__ void mma_bf16(float& c0, float& c1, float& c2, float& c3,
        unsigned a0, unsigned a1, unsigned a2, unsigned a3,
        unsigned b0, unsigned b1) {
    asm volatile("mma.sync.aligned.m16n8k16.row.col.f32.bf16.bf16.f32 "
        "{%0,%1,%2,%3}, {%4,%5,%6,%7}, {%8,%9}, {%0,%1,%2,%3};"
        : "+f"(c0), "+f"(c1), "+f"(c2), "+f"(c3)
        : "r"(a0), "r"(a1), "r"(a2), "r"(a3), "r"(b0), "r"(b1));
}

__device__ __forceinline__ void mma_bf16_k8(float& c0, float& c1, float& c2, float& c3,
        unsigned a0, unsigned a1, unsigned b0) {
    asm volatile("mma.sync.aligned.m16n8k8.row.col.f32.bf16.bf16.f32 "
        "{%0,%1,%2,%3}, {%4,%5}, {%6}, {%0,%1,%2,%3};"
        : "+f"(c0), "+f"(c1), "+f"(c2), "+f"(c3)
        : "r"(a0), "r"(a1), "r"(b0));
}

__device__ __forceinline__ void mma_tf32(float& c0, float& c1, float& c2, float& c3,
        unsigned a0, unsigned a1, unsigned a2, unsigned a3,
        unsigned b0, unsigned b1) {
    asm volatile("mma.sync.aligned.m16n8k8.row.col.f32.tf32.tf32.f32 "
        "{%0,%1,%2,%3}, {%4,%5,%6,%7}, {%8,%9}, {%0,%1,%2,%3};"
        : "+f"(c0), "+f"(c1), "+f"(c2), "+f"(c3)
        : "r"(a0), "r"(a1), "r"(a2), "r"(a3), "r"(b0), "r"(b1));
}

__device__ __forceinline__ unsigned f2tf32(float f) {
    unsigned u;
    asm("cvt.rna.tf32.f32 %0, %1;" : "=r"(u) : "f"(f));
    return u;
}
__device__ __forceinline__ float tf32r(float f) { return __uint_as_float(f2tf32(f)); }

// -------- fused: weight packing (4 jobs) + LN1 in ONE wide launch --------
__device__ void wpackT_body(const float* __restrict__ w, unsigned* __restrict__ out,
                            int N, int K, int n0, int k0, int t, float (*ws)[33]) {
    int r = t >> 5, c = t & 31;
    #pragma unroll
    for (int i = 0; i < 8; i++)
        ws[r + i*8][c] = w[(k0 + r + i*8)*N + n0 + c];
    __syncthreads();
    int n = t >> 3, kp0 = (t & 7)*4;
    unsigned u[4];
    #pragma unroll
    for (int j = 0; j < 4; j++)
        u[j] = pack_bf16(ws[(kp0+j)*2][n], ws[(kp0+j)*2+1][n]);
    *(uint4*)&out[(n0 + n)*(K>>1) + (k0>>1) + kp0] = *(uint4*)u;
}

__global__ void pack_ln_kernel(const float* __restrict__ wout,
                               const float* __restrict__ ffn_w1,
                               const float* __restrict__ ffn_w2,
                               const float* __restrict__ cpb_w1,
                               unsigned* __restrict__ wp,
                               const float* __restrict__ src,
                               const float* __restrict__ gma,
                               const float* __restrict__ bta) {
    __shared__ float ws[64][33];
    int blk = blockIdx.x, t = threadIdx.x;
    if (blk < 128) {
        int i = blk*256 + t;
        float2 v = ((const float2*)wout)[i];
        wp[i] = pack_bf16(v.x, v.y);
    } else if (blk < 256) {
        int idx = blk - 128;
        int n0 = (idx & 31)*32, k0 = (idx >> 5)*64;
        wpackT_body(ffn_w1, wp + 32768, 1024, 256, n0, k0, t, ws);
    } else if (blk < 384) {
        int idx = blk - 256;
        int n0 = (idx & 7)*32, k0 = (idx >> 3)*64;
        wpackT_body(ffn_w2, wp + 163840, 256, 1024, n0, k0, t, ws);
    } else if (blk < 392) {
        int idx = (blk - 384)*256 + t;
        int ll = idx >> 6, rem = idx & 63;
        int nt = rem >> 3, q = rem & 7;
        int kt = q >> 1, reg = q & 1;
        int gg = ll >> 2, ti = ll & 3;
        int k = kt*16 + reg*8 + ti*2;
        int col = nt*8 + gg;
        g_w1v[idx] = pack_bf16(cpb_w1[k*64 + col], cpb_w1[(k+1)*64 + col]);
    } else {
        // LN1: rows (blk-392)*8 .. +8, output to g_x CHW via smem transpose
        float* ys = &ws[0][0];
        int w = t >> 5, l = t & 31;
        int base = (blk - 392)*8;
        int row = base + w;
        const float4* inr = (const float4*)(src + row*256);
        float4 v0 = inr[l*2], v1 = inr[l*2 + 1];
        float s  = v0.x + v0.y + v0.z + v0.w + v1.x + v1.y + v1.z + v1.w;
        float sq = v0.x*v0.x + v0.y*v0.y + v0.z*v0.z + v0.w*v0.w
                 + v1.x*v1.x + v1.y*v1.y + v1.z*v1.z + v1.w*v1.w;
        #pragma unroll
        for (int o = 16; o; o >>= 1) {
            s  += __shfl_xor_sync(0xffffffffu, s,  o);
            sq += __shfl_xor_sync(0xffffffffu, sq, o);
        }
        float m = s * (1.f/256.f);
        float inv = rsqrtf(sq * (1.f/256.f) - m*m + 1e-5f);
        float4 g0 = ((const float4*)gma)[l*2], g1 = ((const float4*)gma)[l*2 + 1];
        float4 b0 = ((const float4*)bta)[l*2], b1 = ((const float4*)bta)[l*2 + 1];
        float y[8] = {
            (v0.x - m)*inv*g0.x + b0.x, (v0.y - m)*inv*g0.y + b0.y,
            (v0.z - m)*inv*g0.z + b0.z, (v0.w - m)*inv*g0.w + b0.w,
            (v1.x - m)*inv*g1.x + b1.x, (v1.y - m)*inv*g1.y + b1.y,
            (v1.z - m)*inv*g1.z + b1.z, (v1.w - m)*inv*g1.w + b1.w };
        #pragma unroll
        for (int k = 0; k < 8; k++) ys[w*256 + l*8 + k] = y[k];
        __syncthreads();
        int b = base >> 10, n0 = base & 1023;
        int ch = t;
        float4 u0 = make_float4(ys[0*256 + ch], ys[1*256 + ch], ys[2*256 + ch], ys[3*256 + ch]);
        float4 u1 = make_float4(ys[4*256 + ch], ys[5*256 + ch], ys[6*256 + ch], ys[7*256 + ch]);
        *(float4*)&g_x[b*CN + ch*1024 + n0]     = u0;
        *(float4*)&g_x[b*CN + ch*1024 + n0 + 4] = u1;
    }
}

// ---------------- LayerNorm (mode-1): warp-per-row -> bf16x2 rows ----------------
__global__ void ln2_kernel(const float* __restrict__ in, const float* __restrict__ gma,
                           const float* __restrict__ bta, unsigned* __restrict__ out) {
    int w = threadIdx.x >> 5, l = threadIdx.x & 31;
    int row = blockIdx.x*8 + w;
    const float4* inr = (const float4*)(in + row*256);
    float4 v0 = inr[l*2], v1 = inr[l*2 + 1];
    float s  = v0.x + v0.y + v0.z + v0.w + v1.x + v1.y + v1.z + v1.w;
    float sq = v0.x*v0.x + v0.y*v0.y + v0.z*v0.z + v0.w*v0.w
             + v1.x*v1.x + v1.y*v1.y + v1.z*v1.z + v1.w*v1.w;
    #pragma unroll
    for (int o = 16; o; o >>= 1) {
        s  += __shfl_xor_sync(0xffffffffu, s,  o);
        sq += __shfl_xor_sync(0xffffffffu, sq, o);
    }
    float m = s * (1.f/256.f);
    float inv = rsqrtf(sq * (1.f/256.f) - m*m + 1e-5f);
    float4 g0 = ((const float4*)gma)[l*2], g1 = ((const float4*)gma)[l*2 + 1];
    float4 b0 = ((const float4*)bta)[l*2], b1 = ((const float4*)bta)[l*2 + 1];
    uint4 u = make_uint4(
        pack_bf16((v0.x - m)*inv*g0.x + b0.x, (v0.y - m)*inv*g0.y + b0.y),
        pack_bf16((v0.z - m)*inv*g0.z + b0.z, (v0.w - m)*inv*g0.w + b0.w),
        pack_bf16((v1.x - m)*inv*g1.x + b1.x, (v1.y - m)*inv*g1.y + b1.y),
        pack_bf16((v1.z - m)*inv*g1.z + b1.z, (v1.w - m)*inv*g1.w + b1.w));
    *(uint4*)&out[row*128 + l*4] = u;
}

// ---------------- grouped 1x1 q projection ----------------
__global__ void qproj_kernel(const float* __restrict__ wq) {
    int bg = blockIdx.x; int b = bg >> 3, g = bg & 7;
    int n0 = blockIdx.y * 128;
    int t = threadIdx.x;
    __shared__ float wqs[1024], xs[32*128];
    for (int i = t; i < 1024; i += 256) wqs[i] = wq[g*1024 + i];
    for (int i = t; i < 4096; i += 256) {
        int c = i >> 7, nn = i & 127;
        xs[c*128 + nn] = g_x[b*CN + (g*32 + c)*1024 + n0 + nn];
    }
    __syncthreads();
    for (int i = t; i < 4096; i += 256) {
        int o = i >> 7, nn = i & 127;
        float a = 0.f;
        #pragma unroll
        for (int c = 0; c < 32; c++) a += xs[c*128 + nn] * wqs[o*32 + c];
        g_q[b*CN + (g*32 + o)*1024 + n0 + nn] = a;
    }
}

// ---- FUSED: depthwise conv + GELU + offset proj + tanh -> vgrid; grid 16 x 128 thr ----
// Thread = (pos, comp). Conv computed inline per channel, reduced straight into offset dot.
__global__ void convoff_kernel(const float* __restrict__ wdw, const float* __restrict__ bdw,
                               const float* __restrict__ woff) {
    int bg = blockIdx.x; int b = bg >> 3, g = bg & 7;
    int t = threadIdx.x;             // 128: pos = t>>1, comp = t&1
    __shared__ float wdws[1152], bdws[32], woffs[64];
    for (int i = t; i < 1152; i += 128) wdws[i] = wdw[i];
    if (t < 32) bdws[t] = bdw[t];
    if (t < 64) woffs[t] = woff[t];
    __syncthreads();
    int pos = t >> 1, comp = t & 1;
    int oy = (pos >> 3)*4 - 1, ox = (pos & 7)*4 - 1;
    const float* qg = g_q + b*CN + g*32*1024;
    float s = 0.f;
    for (int c = 0; c < 32; c++) {
        const float* xc = qg + c*1024;
        const float* wc = wdws + c*36;
        float a = 0.f;
        #pragma unroll
        for (int ky = 0; ky < 6; ky++) {
            int iy = oy + ky;
            if ((unsigned)iy < 32u) {
                #pragma unroll
                for (int kx = 0; kx < 6; kx++) {
                    int ix = ox + kx;
                    if ((unsigned)ix < 32u)
                        a += xc[iy*32 + ix] * wc[ky*6 + kx];
                }
            }
        }
        a += bdws[c];
        float ge = 0.5f * a * (1.f + erff(a * 0.70710678118654752f));
        s += ge * woffs[comp*32 + c];
    }
    float off = tanhf(s) * 4.f;
    float base = comp ? (float)(pos >> 3) : (float)(pos & 7);
    g_vgrid[bg*128 + pos*2 + comp] = 2.f * (base + off) * (1.f/7.f) - 1.f;
}

// ---- FUSED: bilinear grid_sample + k/v proj + CPB bf16 table quarter; grid (16 bg, 4) ----
__global__ void sample_kv_cpbf_kernel(const float* __restrict__ wk, const float* __restrict__ wv) {
    int bg = blockIdx.x; int b = bg >> 3, g = bg & 7;
    int quarter = blockIdx.y;
    int j0 = quarter * 16;
    int t = threadIdx.x;
    __shared__ float samp[32*16], wks[1024], wvs[1024], cds[128];
    for (int i = t; i < 1024; i += 256) { wks[i] = wk[g*1024 + i]; wvs[i] = wv[g*1024 + i]; }
    if (t < 128) cds[t] = g_vgrid[bg*128 + t];
    __syncthreads();
    const float* xg = g_x + b*CN + g*32*1024;
    for (int i = t; i < 512; i += 256) {
        int c = i >> 4, jj = i & 15;
        float xf = ((cds[(j0 + jj)*2 + 0] + 1.f)*32.f - 1.f)*0.5f;
        float yf = ((cds[(j0 + jj)*2 + 1] + 1.f)*32.f - 1.f)*0.5f;
        float x0f = floorf(xf), y0f = floorf(yf);
        int x0 = (int)x0f, y0 = (int)y0f;
        float wx1 = xf - x0f, wx0 = 1.f - wx1, wy1 = yf - y0f, wy0 = 1.f - wy1;
        float acc = 0.f;
        #pragma unroll
        for (int dy = 0; dy < 2; dy++) {
            int iy = y0 + dy;
            if ((unsigned)iy >= 32u) continue;
            float wy = dy ? wy1 : wy0;
            #pragma unroll
            for (int dx = 0; dx < 2; dx++) {
                int ix = x0 + dx;
                if ((unsigned)ix >= 32u) continue;
                float wxx = dx ? wx1 : wx0;
                acc += xg[c*1024 + iy*32 + ix] * wxx * wy;
            }
        }
        samp[c*16 + jj] = acc;
    }
    // CPB tables for rows quarter*8 .. +8 (runs in the sampling latency shadow)
    for (int i = quarter*512 + t; i < quarter*512 + 512; i += 256) {
        int ii = i >> 6, j = i & 63;
        float p = 2.f * (float)ii * (1.f/31.f) - 1.f;
        float dx = p - cds[2*j];
        float fx = copysignf(__logf(1.f + fabsf(dx)), dx);
        __nv_bfloat16 vx = __float2bfloat16_rn(fx);
        g_fx[bg*2048 + i] = *(unsigned short*)&vx;
        float dy = p - cds[2*j + 1];
        float fy = copysignf(__logf(1.f + fabsf(dy)), dy);
        __nv_bfloat16 vy = __float2bfloat16_rn(fy);
        g_fy[bg*2048 + i] = *(unsigned short*)&vy;
    }
    __syncthreads();
    for (int i = t; i < 512; i += 256) {
        int o = i >> 4, jj = i & 15;
        float ak = 0.f, av = 0.f;
        #pragma unroll
        for (int c = 0; c < 32; c++) {
            float f = samp[c*16 + jj];
            ak += f * wks[o*32 + c];
            av += f * wvs[o*32 + c];
        }
        g_k[(b*256 + g*32 + o)*64 + j0 + jj] = ak;
        g_v[(b*256 + g*32 + o)*64 + j0 + jj] = av;
    }
}

// -------- fused attention: sim, CPB (3 MMA layers), softmax, attn@v all on tensor cores --------
__global__ __launch_bounds__(256, 4) void attn_kernel(
        const float* __restrict__ w0, const float* __restrict__ b0p,
        const float* __restrict__ b1p,
        const float* __restrict__ w2, const float* __restrict__ b2p) {
    int bh = blockIdx.y; int b = bh >> 3, h = bh & 7;
    int i0 = blockIdx.x * 32;
    int t = threadIdx.x, w = t >> 5, l = t & 31, g = l >> 2, tig = l & 3;

    __shared__ __align__(16) float ks[64*36];
    __shared__ __align__(16) float vs[64*36];
    __shared__ __align__(16) float qs[32*36];
    __shared__ __align__(16) unsigned W1v[32*68];
    __shared__ __align__(16) unsigned pf[2048];
    __shared__ __align__(16) float b1s[64];
    __shared__ __align__(16) float w2s[64];
    __shared__ __align__(16) float logits[32*68];

    if (t < 64) { b1s[t] = b1p[t]; w2s[t] = w2[t]; }
    for (int i = t; i < 2048; i += 256) {
        int d = i >> 6, j = i & 63;
        ks[j*36 + d] = tf32r(g_k[(b*256 + h*32 + d)*64 + j] * 0.17677669529663687f);
        vs[j*36 + d] = tf32r(g_v[(b*256 + h*32 + d)*64 + j]);
    }
    for (int i = t; i < 1024; i += 256) {
        int d = i >> 5, ii = i & 31;
        qs[ii*36 + d] = tf32r(g_q[b*CN + (h*32 + d)*1024 + i0 + ii]);
    }
    for (int i = t; i < 512; i += 256) {
        uint4 u = ((const uint4*)g_w1v)[i];
        int ll = i >> 4, rem4 = (i & 15)*4;
        *(uint4*)&W1v[ll*68 + rem4] = u;
    }
    for (int i = t; i < 2048; i += 256) {
        int j = i & 63;
        unsigned lo = g_fx[bh*2048 + i];
        unsigned hi = g_fy[bh*2048 + blockIdx.x*64 + j];
        pf[i] = lo | (hi << 16);
    }
    unsigned w0b[8];
    #pragma unroll
    for (int nt = 0; nt < 8; nt++) {
        int col = nt*8 + g;
        w0b[nt] = (tig == 0) ? pack_bf16(w0[col], w0[64 + col])
                : (tig == 1) ? pack_bf16(b0p[col], 0.f) : 0u;
    }
    __syncthreads();

    unsigned w2b0[4], w2b1[4];
    #pragma unroll
    for (int kt2 = 0; kt2 < 4; kt2++) {
        if (g == 0) {
            w2b0[kt2] = pack_bf16(w2s[kt2*16 + 2*tig],     w2s[kt2*16 + 2*tig + 1]);
            w2b1[kt2] = pack_bf16(w2s[kt2*16 + 8 + 2*tig], w2s[kt2*16 + 9 + 2*tig]);
        } else { w2b0[kt2] = 0u; w2b1[kt2] = 0u; }
    }

    float b2v = b2p[0];

    // ---- sim = Q K^T via tf32 mma ----
    {
        int m0w = (w & 1) * 16, n0w = (w >> 1) * 16;
        float c[2][4];
        #pragma unroll
        for (int nt = 0; nt < 2; nt++)
            c[nt][0] = c[nt][1] = c[nt][2] = c[nt][3] = 0.f;
        #pragma unroll
        for (int kk = 0; kk < 32; kk += 8) {
            unsigned a0 = __float_as_uint(qs[(m0w + g)*36 + kk + tig]);
            unsigned a1 = __float_as_uint(qs[(m0w + g + 8)*36 + kk + tig]);
            unsigned a2 = __float_as_uint(qs[(m0w + g)*36 + kk + tig + 4]);
            unsigned a3 = __float_as_uint(qs[(m0w + g + 8)*36 + kk + tig + 4]);
            #pragma unroll
            for (int nt = 0; nt < 2; nt++) {
                int j = n0w + nt*8 + g;
                unsigned b0 = __float_as_uint(ks[j*36 + kk + tig]);
                unsigned b1 = __float_as_uint(ks[j*36 + kk + tig + 4]);
                mma_tf32(c[nt][0], c[nt][1], c[nt][2], c[nt][3], a0, a1, a2, a3, b0, b1);
            }
        }
        #pragma unroll
        for (int nt = 0; nt < 2; nt++) {
            int col = n0w + nt*8 + 2*tig;
            *(float2*)&logits[(m0w + g)*68 + col]     = make_float2(c[nt][0] + b2v, c[nt][1] + b2v);
            *(float2*)&logits[(m0w + g + 8)*68 + col] = make_float2(c[nt][2] + b2v, c[nt][3] + b2v);
        }
    }
    __syncthreads();

    // ---- CPB bias: 3 MLP stages on bf16 HMMA (layer-0 uses k8 mma) ----
    const uint4* W1v4 = (const uint4*)W1v;
    const float2* b1s2 = (const float2*)b1s;
    const unsigned ONE_PACK = 0x00003F80u;
    int pbase = w*256;
    for (int mt = 0; mt < 16; mt++) {
        int p0 = pbase + mt*16 + g;
        int p1 = p0 + 8;
        unsigned pf0 = pf[p0], pf1 = pf[p1];
        unsigned af0 = (tig == 0) ? pf0 : (tig == 1) ? ONE_PACK : 0u;
        unsigned af1 = (tig == 0) ? pf1 : (tig == 1) ? ONE_PACK : 0u;

        float hc[8][4];
        #pragma unroll
        for (int nt = 0; nt < 8; nt++) {
            hc[nt][0] = hc[nt][1] = hc[nt][2] = hc[nt][3] = 0.f;
            mma_bf16_k8(hc[nt][0], hc[nt][1], hc[nt][2], hc[nt][3], af0, af1, w0b[nt]);
        }
        unsigned a[4][4];
        #pragma unroll
        for (int kt = 0; kt < 4; kt++) {
            a[kt][0] = pack_bf16(fmaxf(hc[2*kt][0], 0.f),   fmaxf(hc[2*kt][1], 0.f));
            a[kt][1] = pack_bf16(fmaxf(hc[2*kt][2], 0.f),   fmaxf(hc[2*kt][3], 0.f));
            a[kt][2] = pack_bf16(fmaxf(hc[2*kt+1][0], 0.f), fmaxf(hc[2*kt+1][1], 0.f));
            a[kt][3] = pack_bf16(fmaxf(hc[2*kt+1][2], 0.f), fmaxf(hc[2*kt+1][3], 0.f));
        }

        float d0 = 0.f, d1 = 0.f, d2 = 0.f, d3 = 0.f;
        #pragma unroll
        for (int kt2 = 0; kt2 < 4; kt2++) {
            int nt0 = 2*kt2, nt1 = nt0 + 1;
            uint4 ua = W1v4[l*17 + nt0*2], ub = W1v4[l*17 + nt0*2 + 1];
            float c00 = 0.f, c01 = 0.f, c02 = 0.f, c03 = 0.f;
            mma_bf16(c00, c01, c02, c03, a[0][0], a[0][1], a[0][2], a[0][3], ua.x, ua.y);
            mma_bf16(c00, c01, c02, c03, a[1][0], a[1][1], a[1][2], a[1][3], ua.z, ua.w);
            mma_bf16(c00, c01, c02, c03, a[2][0], a[2][1], a[2][2], a[2][3], ub.x, ub.y);
            mma_bf16(c00, c01, c02, c03, a[3][0], a[3][1], a[3][2], a[3][3], ub.z, ub.w);
            uint4 uc = W1v4[l*17 + nt1*2], ud = W1v4[l*17 + nt1*2 + 1];
            float c10 = 0.f, c11 = 0.f, c12 = 0.f, c13 = 0.f;
            mma_bf16(c10, c11, c12, c13, a[0][0], a[0][1], a[0][2], a[0][3], uc.x, uc.y);
            mma_bf16(c10, c11, c12, c13, a[1][0], a[1][1], a[1][2], a[1][3], uc.z, uc.w);
            mma_bf16(c10, c11, c12, c13, a[2][0], a[2][1], a[2][2], a[2][3], ud.x, ud.y);
            mma_bf16(c10, c11, c12, c13, a[3][0], a[3][1], a[3][2], a[3][3], ud.z, ud.w);
            float2 bv0 = b1s2[nt0*4 + tig];
            float2 bv1 = b1s2[nt1*4 + tig];
            unsigned q0 = pack_bf16(fmaxf(c00 + bv0.x, 0.f), fmaxf(c01 + bv0.y, 0.f));
            unsigned q1 = pack_bf16(fmaxf(c02 + bv0.x, 0.f), fmaxf(c03 + bv0.y, 0.f));
            unsigned q2 = pack_bf16(fmaxf(c10 + bv1.x, 0.f), fmaxf(c11 + bv1.y, 0.f));
            unsigned q3 = pack_bf16(fmaxf(c12 + bv1.x, 0.f), fmaxf(c13 + bv1.y, 0.f));
            mma_bf16(d0, d1, d2, d3, q0, q1, q2, q3, w2b0[kt2], w2b1[kt2]);
        }
        if (tig == 0) {
            logits[(p0 >> 6)*68 + (p0 & 63)] += d0;
            logits[(p1 >> 6)*68 + (p1 & 63)] += d2;
        }
    }
    __syncthreads();

    // ---- softmax over j=64 per row ----
    for (int rr = 0; rr < 4; rr++) {
        int row = w*4 + rr;
        float l0 = logits[row*68 + l], l1 = logits[row*68 + 32 + l];
        float m = fmaxf(l0, l1);
        #pragma unroll
        for (int o = 16; o; o >>= 1) m = fmaxf(m, __shfl_xor_sync(0xffffffffu, m, o));
        float e0 = __expf(l0 - m), e1 = __expf(l1 - m);
        float ss = e0 + e1;
        #pragma unroll
        for (int o = 16; o; o >>= 1) ss += __shfl_xor_sync(0xffffffffu, ss, o);
        float inv = 1.f / ss;
        logits[row*68 + l] = tf32r(e0*inv);
        logits[row*68 + 32 + l] = tf32r(e1*inv);
    }
    __syncthreads();

    // ---- attn @ v via tf32 mma; output packed bf16x2 ----
    {
        int mw2 = (w & 1) * 16, n0v = (w >> 1) * 8;
        float c0 = 0.f, c1 = 0.f, c2 = 0.f, c3 = 0.f;
        #pragma unroll
        for (int kk = 0; kk < 64; kk += 8) {
            unsigned a0 = __float_as_uint(logits[(mw2 + g)*68 + kk + tig]);
            unsigned a1 = __float_as_uint(logits[(mw2 + g + 8)*68 + kk + tig]);
            unsigned a2 = __float_as_uint(logits[(mw2 + g)*68 + kk + tig + 4]);
            unsigned a3 = __float_as_uint(logits[(mw2 + g + 8)*68 + kk + tig + 4]);
            unsigned b0 = __float_as_uint(vs[(kk + tig)*36 + n0v + g]);
            unsigned b1 = __float_as_uint(vs[(kk + tig + 4)*36 + n0v + g]);
            mma_tf32(c0, c1, c2, c3, a0, a1, a2, a3, b0, b1);
        }
        int colp = (h*32 + n0v)/2 + tig;
        g_attn[(b*1024 + i0 + mw2 + g)*128 + colp]     = pack_bf16(c0, c1);
        g_attn[(b*1024 + i0 + mw2 + g + 8)*128 + colp] = pack_bf16(c2, c3);
    }
}

// ---------------- bf16 tensor-core GEMM; A [M][K2], B [N][K2] bf16x2 pre-packed ----------------
template<int BM, int EPI>
__global__ __launch_bounds__(BM*2) void gemm_bf16(
        const unsigned* __restrict__ A, const unsigned* __restrict__ B,
        const float* __restrict__ bias, const float* __restrict__ res,
        void* __restrict__ Cv, int M, int N, int K2) {
    const int m0 = blockIdx.y * BM, n0 = blockIdx.x * 64;
    constexpr int WM = BM / 32;
    constexpr int NBB = (BM == 128) ? 1 : 2;
    __shared__ __align__(16) unsigned As[BM*20];
    __shared__ __align__(16) unsigned Bs[64*20];
    int t = threadIdx.x, w = t >> 5, l = t & 31, g = l >> 2, ti = l & 3;
    int mw = (w % WM)*32, nw = (w / WM)*32;

    float c[2][4][4];
    #pragma unroll
    for (int mt = 0; mt < 2; mt++)
        #pragma unroll
        for (int nt = 0; nt < 4; nt++)
            c[mt][nt][0] = c[mt][nt][1] = c[mt][nt][2] = c[mt][nt][3] = 0.f;

    int ra = t >> 1, ca = (t & 1)*8;
    int rb = (BM == 128) ? (t >> 2) : (t >> 1);
    int cb = (BM == 128) ? (t & 3)*4 : (t & 1)*8;

    uint4 pa0 = *(const uint4*)&A[(m0 + ra)*K2 + ca];
    uint4 pa1 = *(const uint4*)&A[(m0 + ra)*K2 + ca + 4];
    uint4 pb[NBB];
    #pragma unroll
    for (int u = 0; u < NBB; u++) pb[u] = *(const uint4*)&B[(n0 + rb)*K2 + cb + u*4];

    for (int k0 = 0; k0 < K2; k0 += 16) {
        *(uint4*)&As[ra*20 + ca]     = pa0;
        *(uint4*)&As[ra*20 + ca + 4] = pa1;
        #pragma unroll
        for (int u = 0; u < NBB; u++) *(uint4*)&Bs[rb*20 + cb + u*4] = pb[u];
        __syncthreads();
        if (k0 + 16 < K2) {
            pa0 = *(const uint4*)&A[(m0 + ra)*K2 + k0 + 16 + ca];
            pa1 = *(const uint4*)&A[(m0 + ra)*K2 + k0 + 16 + ca + 4];
            #pragma unroll
            for (int u = 0; u < NBB; u++)
                pb[u] = *(const uint4*)&B[(n0 + rb)*K2 + k0 + 16 + cb + u*4];
        }
        #pragma unroll
        for (int kk = 0; kk < 16; kk += 8) {
            unsigned a[2][4];
            #pragma unroll
            for (int mt = 0; mt < 2; mt++) {
                int r = mw + mt*16 + g;
                a[mt][0] = As[r*20 + kk + ti];
                a[mt][1] = As[(r + 8)*20 + kk + ti];
                a[mt][2] = As[r*20 + kk + ti + 4];
                a[mt][3] = As[(r + 8)*20 + kk + ti + 4];
            }
            #pragma unroll
            for (int nt = 0; nt < 4; nt++) {
                int nc = nw + nt*8 + g;
                unsigned b0 = Bs[nc*20 + kk + ti];
                unsigned b1 = Bs[nc*20 + kk + ti + 4];
                #pragma unroll
                for (int mt = 0; mt < 2; mt++)
                    mma_bf16(c[mt][nt][0], c[mt][nt][1], c[mt][nt][2], c[mt][nt][3],
                             a[mt][0], a[mt][1], a[mt][2], a[mt][3], b0, b1);
            }
        }
        __syncthreads();
    }
    #pragma unroll
    for (int mt = 0; mt < 2; mt++) {
        #pragma unroll
        for (int nt = 0; nt < 4; nt++) {
            int col = n0 + nw + nt*8 + 2*ti;
            int r0 = m0 + mw + mt*16 + g, r1 = r0 + 8;
            float2 bi = *(const float2*)&bias[col];
            if (EPI == 1) {
                unsigned* C = (unsigned*)Cv;
                int N2 = N >> 1;
                C[r0*N2 + (col >> 1)] = pack_bf16(fmaxf(c[mt][nt][0] + bi.x, 0.f),
                                                  fmaxf(c[mt][nt][1] + bi.y, 0.f));
                C[r1*N2 + (col >> 1)] = pack_bf16(fmaxf(c[mt][nt][2] + bi.x, 0.f),
                                                  fmaxf(c[mt][nt][3] + bi.y, 0.f));
            } else {
                float* C = (float*)Cv;
                float2 r0v = *(const float2*)&res[r0*N + col];
                float2 r1v = *(const float2*)&res[r1*N + col];
                *(float2*)&C[r0*N + col] = make_float2(c[mt][nt][0] + bi.x + r0v.x,
                                                       c[mt][nt][1] + bi.y + r0v.y);
                *(float2*)&C[r1*N + col] = make_float2(c[mt][nt][2] + bi.x + r1v.x,
                                                       c[mt][nt][3] + bi.y + r1v.y);
            }
        }
    }
}

// ---------------- launcher ----------------
extern "C" void kernel_launch(void* const* d_in, const int* in_sizes, int n_in,
                              void* d_out, int out_size) {
    const float* src     = (const float*)d_in[0];
    const float* norm1_g = (const float*)d_in[1];
    const float* norm1_b = (const float*)d_in[2];
    const float* wq      = (const float*)d_in[3];
    const float* wdw     = (const float*)d_in[4];
    const float* bdw     = (const float*)d_in[5];
    const float* woff    = (const float*)d_in[6];
    const float* wk      = (const float*)d_in[7];
    const float* wv      = (const float*)d_in[8];
    const float* cpb_w0  = (const float*)d_in[9];
    const float* cpb_b0  = (const float*)d_in[10];
    const float* cpb_w1  = (const float*)d_in[11];
    const float* cpb_b1  = (const float*)d_in[12];
    const float* cpb_w2  = (const float*)d_in[13];
    const float* cpb_b2  = (const float*)d_in[14];
    const float* wout    = (const float*)d_in[15];
    const float* bout    = (const float*)d_in[16];
    const float* norm2_g = (const float*)d_in[17];
    const float* norm2_b = (const float*)d_in[18];
    const float* ffn_w1  = (const float*)d_in[19];
    const float* ffn_b1  = (const float*)d_in[20];
    const float* ffn_w2  = (const float*)d_in[21];
    const float* ffn_b2  = (const float*)d_in[22];

    void *p_attn, *p_srcp, *p_src2, *p_ffnh, *p_wp;
    cudaGetSymbolAddress(&p_attn, g_attn);
    cudaGetSymbolAddress(&p_srcp, g_srcp);
    cudaGetSymbolAddress(&p_src2, g_src2);
    cudaGetSymbolAddress(&p_ffnh, g_ffnh);
    cudaGetSymbolAddress(&p_wp,   g_wp);
    unsigned* wp = (unsigned*)p_wp;

    pack_ln_kernel<<<648, 256>>>(wout, ffn_w1, ffn_w2, cpb_w1, wp, src, norm1_g, norm1_b);
    qproj_kernel<<<dim3(16, 8), 256>>>(wq);
    convoff_kernel<<<16, 128>>>(wdw, bdw, woff);
    sample_kv_cpbf_kernel<<<dim3(16, 4), 256>>>(wk, wv);
    attn_kernel<<<dim3(32, 16), 256>>>(cpb_w0, cpb_b0, cpb_b1, cpb_w2, cpb_b2);
    gemm_bf16<64, 0><<<dim3(4, 32), 128>>>((const unsigned*)p_attn, wp, bout, src,
                                           p_srcp, 2048, 256, 128);
    ln2_kernel<<<256, 256>>>((const float*)p_srcp, norm2_g, norm2_b, (unsigned*)p_src2);
    gemm_bf16<128, 1><<<dim3(16, 16), 256>>>((const unsigned*)p_src2, wp + 32768, ffn_b1,
                                             nullptr, p_ffnh, 2048, 1024, 128);
    gemm_bf16<64, 0><<<dim3(4, 32), 128>>>((const unsigned*)p_ffnh, wp + 163840, ffn_b2,
                                           (const float*)p_srcp, d_out, 2048, 256, 512);
}

// round 16
// speedup vs baseline: 1.4483x; 1.4483x over previous
#include <cuda_runtime.h>
#include <cuda_bf16.h>
#include <math.h>

#define CN (256*1024)

// ---------------- device scratch ----------------
__device__ float g_x[2*256*1024];     // LN1 out, (B,C,N)
__device__ float g_q[2*256*1024];     // q proj (B,C,N)
__device__ float g_sg[16*2048];       // depthwise conv + GELU out
__device__ float g_vgrid[16*64*2];    // normalized kv coords per (b,g)
__device__ unsigned short g_fx[16*2048];  // bf16 CPB fx per (bh, ii, j)
__device__ unsigned short g_fy[16*2048];  // bf16 CPB fy per (bh, py, j)
__device__ unsigned g_w1v[2048];      // pre-packed W1 B-fragments (per-lane bf16x2)
__device__ float g_k[2*256*64];
__device__ float g_v[2*256*64];
__device__ unsigned g_attn[2048*128]; // attention out, bf16x2 packed [row][c/2]
__device__ float g_srcp[2*1024*256];  // src + out proj (fp32)
__device__ unsigned g_src2[2048*128]; // LN2 out, bf16x2 packed
__device__ unsigned g_ffnh[2048*512]; // ffn hidden, bf16x2 packed
__device__ unsigned g_wp[294912];     // packed weights: wout[32768] | ffn_w1T[131072] | ffn_w2T[131072]

__device__ __forceinline__ unsigned pack_bf16(float lo, float hi) {
    __nv_bfloat162 v = __floats2bfloat162_rn(lo, hi);
    return *(unsigned*)&v;
}

__device__ __forceinline__ void mma_bf16(float& c0, float& c1, float& c2, float& c3,
        unsigned a0, unsigned a1, unsigned a2, unsigned a3,
        unsigned b0, unsigned b1) {
    asm volatile("mma.sync.aligned.m16n8k16.row.col.f32.bf16.bf16.f32 "
        "{%0,%1,%2,%3}, {%4,%5,%6,%7}, {%8,%9}, {%0,%1,%2,%3};"
        : "+f"(c0), "+f"(c1), "+f"(c2), "+f"(c3)
        : "r"(a0), "r"(a1), "r"(a2), "r"(a3), "r"(b0), "r"(b1));
}

__device__ __forceinline__ void mma_bf16_k8(float& c0, float& c1, float& c2, float& c3,
        unsigned a0, unsigned a1, unsigned b0) {
    asm volatile("mma.sync.aligned.m16n8k8.row.col.f32.bf16.bf16.f32 "
        "{%0,%1,%2,%3}, {%4,%5}, {%6}, {%0,%1,%2,%3};"
        : "+f"(c0), "+f"(c1), "+f"(c2), "+f"(c3)
        : "r"(a0), "r"(a1), "r"(b0));
}

__device__ __forceinline__ void mma_tf32(float& c0, float& c1, float& c2, float& c3,
        unsigned a0, unsigned a1, unsigned a2, unsigned a3,
        unsigned b0, unsigned b1) {
    asm volatile("mma.sync.aligned.m16n8k8.row.col.f32.tf32.tf32.f32 "
        "{%0,%1,%2,%3}, {%4,%5,%6,%7}, {%8,%9}, {%0,%1,%2,%3};"
        : "+f"(c0), "+f"(c1), "+f"(c2), "+f"(c3)
        : "r"(a0), "r"(a1), "r"(a2), "r"(a3), "r"(b0), "r"(b1));
}

__device__ __forceinline__ unsigned f2tf32(float f) {
    unsigned u;
    asm("cvt.rna.tf32.f32 %0, %1;" : "=r"(u) : "f"(f));
    return u;
}
__device__ __forceinline__ float tf32r(float f) { return __uint_as_float(f2tf32(f)); }

// -------- fused: weight packing (4 jobs) + LN1 in ONE wide launch --------
__device__ void wpackT_body(const float* __restrict__ w, unsigned* __restrict__ out,
                            int N, int K, int n0, int k0, int t, float (*ws)[33]) {
    int r = t >> 5, c = t & 31;
    #pragma unroll
    for (int i = 0; i < 8; i++)
        ws[r + i*8][c] = w[(k0 + r + i*8)*N + n0 + c];
    __syncthreads();
    int n = t >> 3, kp0 = (t & 7)*4;
    unsigned u[4];
    #pragma unroll
    for (int j = 0; j < 4; j++)
        u[j] = pack_bf16(ws[(kp0+j)*2][n], ws[(kp0+j)*2+1][n]);
    *(uint4*)&out[(n0 + n)*(K>>1) + (k0>>1) + kp0] = *(uint4*)u;
}

__global__ void pack_ln_kernel(const float* __restrict__ wout,
                               const float* __restrict__ ffn_w1,
                               const float* __restrict__ ffn_w2,
                               const float* __restrict__ cpb_w1,
                               unsigned* __restrict__ wp,
                               const float* __restrict__ src,
                               const float* __restrict__ gma,
                               const float* __restrict__ bta) {
    __shared__ float ws[64][33];
    int blk = blockIdx.x, t = threadIdx.x;
    if (blk < 128) {
        int i = blk*256 + t;
        float2 v = ((const float2*)wout)[i];
        wp[i] = pack_bf16(v.x, v.y);
    } else if (blk < 256) {
        int idx = blk - 128;
        int n0 = (idx & 31)*32, k0 = (idx >> 5)*64;
        wpackT_body(ffn_w1, wp + 32768, 1024, 256, n0, k0, t, ws);
    } else if (blk < 384) {
        int idx = blk - 256;
        int n0 = (idx & 7)*32, k0 = (idx >> 3)*64;
        wpackT_body(ffn_w2, wp + 163840, 256, 1024, n0, k0, t, ws);
    } else if (blk < 392) {
        int idx = (blk - 384)*256 + t;
        int ll = idx >> 6, rem = idx & 63;
        int nt = rem >> 3, q = rem & 7;
        int kt = q >> 1, reg = q & 1;
        int gg = ll >> 2, ti = ll & 3;
        int k = kt*16 + reg*8 + ti*2;
        int col = nt*8 + gg;
        g_w1v[idx] = pack_bf16(cpb_w1[k*64 + col], cpb_w1[(k+1)*64 + col]);
    } else {
        // LN1: rows (blk-392)*8 .. +8, output to g_x CHW via smem transpose
        float* ys = &ws[0][0];
        int w = t >> 5, l = t & 31;
        int base = (blk - 392)*8;
        int row = base + w;
        const float4* inr = (const float4*)(src + row*256);
        float4 v0 = inr[l*2], v1 = inr[l*2 + 1];
        float s  = v0.x + v0.y + v0.z + v0.w + v1.x + v1.y + v1.z + v1.w;
        float sq = v0.x*v0.x + v0.y*v0.y + v0.z*v0.z + v0.w*v0.w
                 + v1.x*v1.x + v1.y*v1.y + v1.z*v1.z + v1.w*v1.w;
        #pragma unroll
        for (int o = 16; o; o >>= 1) {
            s  += __shfl_xor_sync(0xffffffffu, s,  o);
            sq += __shfl_xor_sync(0xffffffffu, sq, o);
        }
        float m = s * (1.f/256.f);
        float inv = rsqrtf(sq * (1.f/256.f) - m*m + 1e-5f);
        float4 g0 = ((const float4*)gma)[l*2], g1 = ((const float4*)gma)[l*2 + 1];
        float4 b0 = ((const float4*)bta)[l*2], b1 = ((const float4*)bta)[l*2 + 1];
        float y[8] = {
            (v0.x - m)*inv*g0.x + b0.x, (v0.y - m)*inv*g0.y + b0.y,
            (v0.z - m)*inv*g0.z + b0.z, (v0.w - m)*inv*g0.w + b0.w,
            (v1.x - m)*inv*g1.x + b1.x, (v1.y - m)*inv*g1.y + b1.y,
            (v1.z - m)*inv*g1.z + b1.z, (v1.w - m)*inv*g1.w + b1.w };
        #pragma unroll
        for (int k = 0; k < 8; k++) ys[w*256 + l*8 + k] = y[k];
        __syncthreads();
        int b = base >> 10, n0 = base & 1023;
        int ch = t;
        float4 u0 = make_float4(ys[0*256 + ch], ys[1*256 + ch], ys[2*256 + ch], ys[3*256 + ch]);
        float4 u1 = make_float4(ys[4*256 + ch], ys[5*256 + ch], ys[6*256 + ch], ys[7*256 + ch]);
        *(float4*)&g_x[b*CN + ch*1024 + n0]     = u0;
        *(float4*)&g_x[b*CN + ch*1024 + n0 + 4] = u1;
    }
}

// ---------------- LayerNorm (mode-1): warp-per-row -> bf16x2 rows ----------------
__global__ void ln2_kernel(const float* __restrict__ in, const float* __restrict__ gma,
                           const float* __restrict__ bta, unsigned* __restrict__ out) {
    int w = threadIdx.x >> 5, l = threadIdx.x & 31;
    int row = blockIdx.x*8 + w;
    const float4* inr = (const float4*)(in + row*256);
    float4 v0 = inr[l*2], v1 = inr[l*2 + 1];
    float s  = v0.x + v0.y + v0.z + v0.w + v1.x + v1.y + v1.z + v1.w;
    float sq = v0.x*v0.x + v0.y*v0.y + v0.z*v0.z + v0.w*v0.w
             + v1.x*v1.x + v1.y*v1.y + v1.z*v1.z + v1.w*v1.w;
    #pragma unroll
    for (int o = 16; o; o >>= 1) {
        s  += __shfl_xor_sync(0xffffffffu, s,  o);
        sq += __shfl_xor_sync(0xffffffffu, sq, o);
    }
    float m = s * (1.f/256.f);
    float inv = rsqrtf(sq * (1.f/256.f) - m*m + 1e-5f);
    float4 g0 = ((const float4*)gma)[l*2], g1 = ((const float4*)gma)[l*2 + 1];
    float4 b0 = ((const float4*)bta)[l*2], b1 = ((const float4*)bta)[l*2 + 1];
    uint4 u = make_uint4(
        pack_bf16((v0.x - m)*inv*g0.x + b0.x, (v0.y - m)*inv*g0.y + b0.y),
        pack_bf16((v0.z - m)*inv*g0.z + b0.z, (v0.w - m)*inv*g0.w + b0.w),
        pack_bf16((v1.x - m)*inv*g1.x + b1.x, (v1.y - m)*inv*g1.y + b1.y),
        pack_bf16((v1.z - m)*inv*g1.z + b1.z, (v1.w - m)*inv*g1.w + b1.w));
    *(uint4*)&out[row*128 + l*4] = u;
}

// ---------------- grouped 1x1 q projection ----------------
__global__ void qproj_kernel(const float* __restrict__ wq) {
    int bg = blockIdx.x; int b = bg >> 3, g = bg & 7;
    int n0 = blockIdx.y * 128;
    int t = threadIdx.x;
    __shared__ float wqs[1024], xs[32*128];
    for (int i = t; i < 1024; i += 256) wqs[i] = wq[g*1024 + i];
    for (int i = t; i < 4096; i += 256) {
        int c = i >> 7, nn = i & 127;
        xs[c*128 + nn] = g_x[b*CN + (g*32 + c)*1024 + n0 + nn];
    }
    __syncthreads();
    for (int i = t; i < 4096; i += 256) {
        int o = i >> 7, nn = i & 127;
        float a = 0.f;
        #pragma unroll
        for (int c = 0; c < 32; c++) a += xs[c*128 + nn] * wqs[o*32 + c];
        g_q[b*CN + (g*32 + o)*1024 + n0 + nn] = a;
    }
}

// ---- depthwise conv(6x6,s4,p1) + GELU; 2 ch/block, 128 thr; grid (16 bg, 16 c-chunks) ----
__global__ void conv_kernel(const float* __restrict__ wdw, const float* __restrict__ bdw) {
    int bg = blockIdx.x; int b = bg >> 3, g = bg & 7;
    int c0 = blockIdx.y * 2;
    int t = threadIdx.x;
    __shared__ float xs[2*1024];
    __shared__ float wdws[2*36], bdws[2];
    if (t < 72) wdws[t] = wdw[c0*36 + t];
    if (t < 2) bdws[t] = bdw[c0 + t];
    const float* qg = g_q + b*CN + (g*32 + c0)*1024;
    #pragma unroll
    for (int i = 0; i < 4; i++)
        *(float4*)&xs[(i*128 + t)*4] = *(const float4*)&qg[(i*128 + t)*4];
    __syncthreads();
    int c = t >> 6, pos = t & 63, oy = (pos >> 3)*4 - 1, ox = (pos & 7)*4 - 1;
    const float* xc = xs + c*1024;
    const float* wc = wdws + c*36;
    float a = 0.f;
    #pragma unroll
    for (int ky = 0; ky < 6; ky++) {
        int iy = oy + ky;
        if ((unsigned)iy < 32u) {
            #pragma unroll
            for (int kx = 0; kx < 6; kx++) {
                int ix = ox + kx;
                if ((unsigned)ix < 32u)
                    a += xc[iy*32 + ix] * wc[ky*6 + kx];
            }
        }
    }
    a += bdws[c];
    g_sg[bg*2048 + (c0 + c)*64 + pos] = 0.5f * a * (1.f + erff(a * 0.70710678118654752f));
}

// ---- offset proj + tanh -> grid coords + CPB bf16 tables; grid (16 bg, 4 quarters) ----
__global__ void offsets_cpbf_kernel(const float* __restrict__ woff) {
    int bg = blockIdx.x;
    int quarter = blockIdx.y;
    int t = threadIdx.x;
    __shared__ float cds[128];
    if (t < 128) {
        int pos = t >> 1, comp = t & 1;
        const float* sg = g_sg + bg*2048;
        float s = 0.f;
        #pragma unroll
        for (int c = 0; c < 32; c++) s += sg[c*64 + pos] * woff[comp*32 + c];
        float off = tanhf(s) * 4.f;
        float base = comp ? (float)(pos >> 3) : (float)(pos & 7);
        float gn = 2.f * (base + off) * (1.f/7.f) - 1.f;
        cds[pos*2 + comp] = gn;
        if (quarter == 0) g_vgrid[bg*128 + pos*2 + comp] = gn;
    }
    __syncthreads();
    for (int i = quarter*512 + t; i < quarter*512 + 512; i += 256) {
        int ii = i >> 6, j = i & 63;
        float p = 2.f * (float)ii * (1.f/31.f) - 1.f;
        float dx = p - cds[2*j];
        float fx = copysignf(__logf(1.f + fabsf(dx)), dx);
        __nv_bfloat16 vx = __float2bfloat16_rn(fx);
        g_fx[bg*2048 + i] = *(unsigned short*)&vx;
        float dy = p - cds[2*j + 1];
        float fy = copysignf(__logf(1.f + fabsf(dy)), dy);
        __nv_bfloat16 vy = __float2bfloat16_rn(fy);
        g_fy[bg*2048 + i] = *(unsigned short*)&vy;
    }
}

// ---- bilinear grid_sample + k/v proj; grid (16 bg, 4 j-chunks) ----
__global__ void sample_kv_kernel(const float* __restrict__ wk, const float* __restrict__ wv) {
    int bg = blockIdx.x; int b = bg >> 3, g = bg & 7;
    int j0 = blockIdx.y * 16;
    int t = threadIdx.x;
    __shared__ float samp[32*16], wks[1024], wvs[1024], cds[32];
    for (int i = t; i < 1024; i += 256) { wks[i] = wk[g*1024 + i]; wvs[i] = wv[g*1024 + i]; }
    if (t < 32) cds[t] = g_vgrid[bg*128 + j0*2 + t];
    __syncthreads();
    const float* xg = g_x + b*CN + g*32*1024;
    for (int i = t; i < 512; i += 256) {
        int c = i >> 4, jj = i & 15;
        float xf = ((cds[jj*2 + 0] + 1.f)*32.f - 1.f)*0.5f;
        float yf = ((cds[jj*2 + 1] + 1.f)*32.f - 1.f)*0.5f;
        float x0f = floorf(xf), y0f = floorf(yf);
        int x0 = (int)x0f, y0 = (int)y0f;
        float wx1 = xf - x0f, wx0 = 1.f - wx1, wy1 = yf - y0f, wy0 = 1.f - wy1;
        float acc = 0.f;
        #pragma unroll
        for (int dy = 0; dy < 2; dy++) {
            int iy = y0 + dy;
            if ((unsigned)iy >= 32u) continue;
            float wy = dy ? wy1 : wy0;
            #pragma unroll
            for (int dx = 0; dx < 2; dx++) {
                int ix = x0 + dx;
                if ((unsigned)ix >= 32u) continue;
                float wxx = dx ? wx1 : wx0;
                acc += xg[c*1024 + iy*32 + ix] * wxx * wy;
            }
        }
        samp[c*16 + jj] = acc;
    }
    __syncthreads();
    for (int i = t; i < 512; i += 256) {
        int o = i >> 4, jj = i & 15;
        float ak = 0.f, av = 0.f;
        #pragma unroll
        for (int c = 0; c < 32; c++) {
            float f = samp[c*16 + jj];
            ak += f * wks[o*32 + c];
            av += f * wvs[o*32 + c];
        }
        g_k[(b*256 + g*32 + o)*64 + j0 + jj] = ak;
        g_v[(b*256 + g*32 + o)*64 + j0 + jj] = av;
    }
}

// -------- fused attention: sim, CPB (3 MMA layers), softmax, attn@v all on tensor cores --------
__global__ __launch_bounds__(256, 4) void attn_kernel(
        const float* __restrict__ w0, const float* __restrict__ b0p,
        const float* __restrict__ b1p,
        const float* __restrict__ w2, const float* __restrict__ b2p) {
    int bh = blockIdx.y; int b = bh >> 3, h = bh & 7;
    int i0 = blockIdx.x * 32;
    int t = threadIdx.x, w = t >> 5, l = t & 31, g = l >> 2, tig = l & 3;

    __shared__ __align__(16) float ks[64*36];
    __shared__ __align__(16) float vs[64*36];
    __shared__ __align__(16) float qs[32*36];
    __shared__ __align__(16) unsigned W1v[32*68];
    __shared__ __align__(16) unsigned pf[2048];
    __shared__ __align__(16) float b1s[64];
    __shared__ __align__(16) float w2s[64];
    __shared__ __align__(16) float logits[32*68];

    if (t < 64) { b1s[t] = b1p[t]; w2s[t] = w2[t]; }
    for (int i = t; i < 2048; i += 256) {
        int d = i >> 6, j = i & 63;
        ks[j*36 + d] = tf32r(g_k[(b*256 + h*32 + d)*64 + j] * 0.17677669529663687f);
        vs[j*36 + d] = tf32r(g_v[(b*256 + h*32 + d)*64 + j]);
    }
    for (int i = t; i < 1024; i += 256) {
        int d = i >> 5, ii = i & 31;
        qs[ii*36 + d] = tf32r(g_q[b*CN + (h*32 + d)*1024 + i0 + ii]);
    }
    for (int i = t; i < 512; i += 256) {
        uint4 u = ((const uint4*)g_w1v)[i];
        int ll = i >> 4, rem4 = (i & 15)*4;
        *(uint4*)&W1v[ll*68 + rem4] = u;
    }
    for (int i = t; i < 2048; i += 256) {
        int j = i & 63;
        unsigned lo = g_fx[bh*2048 + i];
        unsigned hi = g_fy[bh*2048 + blockIdx.x*64 + j];
        pf[i] = lo | (hi << 16);
    }
    unsigned w0b[8];
    #pragma unroll
    for (int nt = 0; nt < 8; nt++) {
        int col = nt*8 + g;
        w0b[nt] = (tig == 0) ? pack_bf16(w0[col], w0[64 + col])
                : (tig == 1) ? pack_bf16(b0p[col], 0.f) : 0u;
    }
    __syncthreads();

    unsigned w2b0[4], w2b1[4];
    #pragma unroll
    for (int kt2 = 0; kt2 < 4; kt2++) {
        if (g == 0) {
            w2b0[kt2] = pack_bf16(w2s[kt2*16 + 2*tig],     w2s[kt2*16 + 2*tig + 1]);
            w2b1[kt2] = pack_bf16(w2s[kt2*16 + 8 + 2*tig], w2s[kt2*16 + 9 + 2*tig]);
        } else { w2b0[kt2] = 0u; w2b1[kt2] = 0u; }
    }

    float b2v = b2p[0];

    // ---- sim = Q K^T via tf32 mma ----
    {
        int m0w = (w & 1) * 16, n0w = (w >> 1) * 16;
        float c[2][4];
        #pragma unroll
        for (int nt = 0; nt < 2; nt++)
            c[nt][0] = c[nt][1] = c[nt][2] = c[nt][3] = 0.f;
        #pragma unroll
        for (int kk = 0; kk < 32; kk += 8) {
            unsigned a0 = __float_as_uint(qs[(m0w + g)*36 + kk + tig]);
            unsigned a1 = __float_as_uint(qs[(m0w + g + 8)*36 + kk + tig]);
            unsigned a2 = __float_as_uint(qs[(m0w + g)*36 + kk + tig + 4]);
            unsigned a3 = __float_as_uint(qs[(m0w + g + 8)*36 + kk + tig + 4]);
            #pragma unroll
            for (int nt = 0; nt < 2; nt++) {
                int j = n0w + nt*8 + g;
                unsigned b0 = __float_as_uint(ks[j*36 + kk + tig]);
                unsigned b1 = __float_as_uint(ks[j*36 + kk + tig + 4]);
                mma_tf32(c[nt][0], c[nt][1], c[nt][2], c[nt][3], a0, a1, a2, a3, b0, b1);
            }
        }
        #pragma unroll
        for (int nt = 0; nt < 2; nt++) {
            int col = n0w + nt*8 + 2*tig;
            *(float2*)&logits[(m0w + g)*68 + col]     = make_float2(c[nt][0] + b2v, c[nt][1] + b2v);
            *(float2*)&logits[(m0w + g + 8)*68 + col] = make_float2(c[nt][2] + b2v, c[nt][3] + b2v);
        }
    }
    __syncthreads();

    // ---- CPB bias: 3 MLP stages on bf16 HMMA (layer-0 uses k8 mma) ----
    const uint4* W1v4 = (const uint4*)W1v;
    const float2* b1s2 = (const float2*)b1s;
    const unsigned ONE_PACK = 0x00003F80u;
    int pbase = w*256;
    for (int mt = 0; mt < 16; mt++) {
        int p0 = pbase + mt*16 + g;
        int p1 = p0 + 8;
        unsigned pf0 = pf[p0], pf1 = pf[p1];
        unsigned af0 = (tig == 0) ? pf0 : (tig == 1) ? ONE_PACK : 0u;
        unsigned af1 = (tig == 0) ? pf1 : (tig == 1) ? ONE_PACK : 0u;

        float hc[8][4];
        #pragma unroll
        for (int nt = 0; nt < 8; nt++) {
            hc[nt][0] = hc[nt][1] = hc[nt][2] = hc[nt][3] = 0.f;
            mma_bf16_k8(hc[nt][0], hc[nt][1], hc[nt][2], hc[nt][3], af0, af1, w0b[nt]);
        }
        unsigned a[4][4];
        #pragma unroll
        for (int kt = 0; kt < 4; kt++) {
            a[kt][0] = pack_bf16(fmaxf(hc[2*kt][0], 0.f),   fmaxf(hc[2*kt][1], 0.f));
            a[kt][1] = pack_bf16(fmaxf(hc[2*kt][2], 0.f),   fmaxf(hc[2*kt][3], 0.f));
            a[kt][2] = pack_bf16(fmaxf(hc[2*kt+1][0], 0.f), fmaxf(hc[2*kt+1][1], 0.f));
            a[kt][3] = pack_bf16(fmaxf(hc[2*kt+1][2], 0.f), fmaxf(hc[2*kt+1][3], 0.f));
        }

        float d0 = 0.f, d1 = 0.f, d2 = 0.f, d3 = 0.f;
        #pragma unroll
        for (int kt2 = 0; kt2 < 4; kt2++) {
            int nt0 = 2*kt2, nt1 = nt0 + 1;
            uint4 ua = W1v4[l*17 + nt0*2], ub = W1v4[l*17 + nt0*2 + 1];
            float c00 = 0.f, c01 = 0.f, c02 = 0.f, c03 = 0.f;
            mma_bf16(c00, c01, c02, c03, a[0][0], a[0][1], a[0][2], a[0][3], ua.x, ua.y);
            mma_bf16(c00, c01, c02, c03, a[1][0], a[1][1], a[1][2], a[1][3], ua.z, ua.w);
            mma_bf16(c00, c01, c02, c03, a[2][0], a[2][1], a[2][2], a[2][3], ub.x, ub.y);
            mma_bf16(c00, c01, c02, c03, a[3][0], a[3][1], a[3][2], a[3][3], ub.z, ub.w);
            uint4 uc = W1v4[l*17 + nt1*2], ud = W1v4[l*17 + nt1*2 + 1];
            float c10 = 0.f, c11 = 0.f, c12 = 0.f, c13 = 0.f;
            mma_bf16(c10, c11, c12, c13, a[0][0], a[0][1], a[0][2], a[0][3], uc.x, uc.y);
            mma_bf16(c10, c11, c12, c13, a[1][0], a[1][1], a[1][2], a[1][3], uc.z, uc.w);
            mma_bf16(c10, c11, c12, c13, a[2][0], a[2][1], a[2][2], a[2][3], ud.x, ud.y);
            mma_bf16(c10, c11, c12, c13, a[3][0], a[3][1], a[3][2], a[3][3], ud.z, ud.w);
            float2 bv0 = b1s2[nt0*4 + tig];
            float2 bv1 = b1s2[nt1*4 + tig];
            unsigned q0 = pack_bf16(fmaxf(c00 + bv0.x, 0.f), fmaxf(c01 + bv0.y, 0.f));
            unsigned q1 = pack_bf16(fmaxf(c02 + bv0.x, 0.f), fmaxf(c03 + bv0.y, 0.f));
            unsigned q2 = pack_bf16(fmaxf(c10 + bv1.x, 0.f), fmaxf(c11 + bv1.y, 0.f));
            unsigned q3 = pack_bf16(fmaxf(c12 + bv1.x, 0.f), fmaxf(c13 + bv1.y, 0.f));
            mma_bf16(d0, d1, d2, d3, q0, q1, q2, q3, w2b0[kt2], w2b1[kt2]);
        }
        if (tig == 0) {
            logits[(p0 >> 6)*68 + (p0 & 63)] += d0;
            logits[(p1 >> 6)*68 + (p1 & 63)] += d2;
        }
    }
    __syncthreads();

    // ---- softmax over j=64 per row ----
    for (int rr = 0; rr < 4; rr++) {
        int row = w*4 + rr;
        float l0 = logits[row*68 + l], l1 = logits[row*68 + 32 + l];
        float m = fmaxf(l0, l1);
        #pragma unroll
        for (int o = 16; o; o >>= 1) m = fmaxf(m, __shfl_xor_sync(0xffffffffu, m, o));
        float e0 = __expf(l0 - m), e1 = __expf(l1 - m);
        float ss = e0 + e1;
        #pragma unroll
        for (int o = 16; o; o >>= 1) ss += __shfl_xor_sync(0xffffffffu, ss, o);
        float inv = 1.f / ss;
        logits[row*68 + l] = tf32r(e0*inv);
        logits[row*68 + 32 + l] = tf32r(e1*inv);
    }
    __syncthreads();

    // ---- attn @ v via tf32 mma; output packed bf16x2 ----
    {
        int mw2 = (w & 1) * 16, n0v = (w >> 1) * 8;
        float c0 = 0.f, c1 = 0.f, c2 = 0.f, c3 = 0.f;
        #pragma unroll
        for (int kk = 0; kk < 64; kk += 8) {
            unsigned a0 = __float_as_uint(logits[(mw2 + g)*68 + kk + tig]);
            unsigned a1 = __float_as_uint(logits[(mw2 + g + 8)*68 + kk + tig]);
            unsigned a2 = __float_as_uint(logits[(mw2 + g)*68 + kk + tig + 4]);
            unsigned a3 = __float_as_uint(logits[(mw2 + g + 8)*68 + kk + tig + 4]);
            unsigned b0 = __float_as_uint(vs[(kk + tig)*36 + n0v + g]);
            unsigned b1 = __float_as_uint(vs[(kk + tig + 4)*36 + n0v + g]);
            mma_tf32(c0, c1, c2, c3, a0, a1, a2, a3, b0, b1);
        }
        int colp = (h*32 + n0v)/2 + tig;
        g_attn[(b*1024 + i0 + mw2 + g)*128 + colp]     = pack_bf16(c0, c1);
        g_attn[(b*1024 + i0 + mw2 + g + 8)*128 + colp] = pack_bf16(c2, c3);
    }
}

// ---------------- bf16 tensor-core GEMM; A [M][K2], B [N][K2] bf16x2 pre-packed ----------------
template<int BM, int EPI>
__global__ __launch_bounds__(BM*2) void gemm_bf16(
        const unsigned* __restrict__ A, const unsigned* __restrict__ B,
        const float* __restrict__ bias, const float* __restrict__ res,
        void* __restrict__ Cv, int M, int N, int K2) {
    const int m0 = blockIdx.y * BM, n0 = blockIdx.x * 64;
    constexpr int WM = BM / 32;
    constexpr int NBB = (BM == 128) ? 1 : 2;
    __shared__ __align__(16) unsigned As[BM*20];
    __shared__ __align__(16) unsigned Bs[64*20];
    int t = threadIdx.x, w = t >> 5, l = t & 31, g = l >> 2, ti = l & 3;
    int mw = (w % WM)*32, nw = (w / WM)*32;

    float c[2][4][4];
    #pragma unroll
    for (int mt = 0; mt < 2; mt++)
        #pragma unroll
        for (int nt = 0; nt < 4; nt++)
            c[mt][nt][0] = c[mt][nt][1] = c[mt][nt][2] = c[mt][nt][3] = 0.f;

    int ra = t >> 1, ca = (t & 1)*8;
    int rb = (BM == 128) ? (t >> 2) : (t >> 1);
    int cb = (BM == 128) ? (t & 3)*4 : (t & 1)*8;

    uint4 pa0 = *(const uint4*)&A[(m0 + ra)*K2 + ca];
    uint4 pa1 = *(const uint4*)&A[(m0 + ra)*K2 + ca + 4];
    uint4 pb[NBB];
    #pragma unroll
    for (int u = 0; u < NBB; u++) pb[u] = *(const uint4*)&B[(n0 + rb)*K2 + cb + u*4];

    for (int k0 = 0; k0 < K2; k0 += 16) {
        *(uint4*)&As[ra*20 + ca]     = pa0;
        *(uint4*)&As[ra*20 + ca + 4] = pa1;
        #pragma unroll
        for (int u = 0; u < NBB; u++) *(uint4*)&Bs[rb*20 + cb + u*4] = pb[u];
        __syncthreads();
        if (k0 + 16 < K2) {
            pa0 = *(const uint4*)&A[(m0 + ra)*K2 + k0 + 16 + ca];
            pa1 = *(const uint4*)&A[(m0 + ra)*K2 + k0 + 16 + ca + 4];
            #pragma unroll
            for (int u = 0; u < NBB; u++)
                pb[u] = *(const uint4*)&B[(n0 + rb)*K2 + k0 + 16 + cb + u*4];
        }
        #pragma unroll
        for (int kk = 0; kk < 16; kk += 8) {
            unsigned a[2][4];
            #pragma unroll
            for (int mt = 0; mt < 2; mt++) {
                int r = mw + mt*16 + g;
                a[mt][0] = As[r*20 + kk + ti];
                a[mt][1] = As[(r + 8)*20 + kk + ti];
                a[mt][2] = As[r*20 + kk + ti + 4];
                a[mt][3] = As[(r + 8)*20 + kk + ti + 4];
            }
            #pragma unroll
            for (int nt = 0; nt < 4; nt++) {
                int nc = nw + nt*8 + g;
                unsigned b0 = Bs[nc*20 + kk + ti];
                unsigned b1 = Bs[nc*20 + kk + ti + 4];
                #pragma unroll
                for (int mt = 0; mt < 2; mt++)
                    mma_bf16(c[mt][nt][0], c[mt][nt][1], c[mt][nt][2], c[mt][nt][3],
                             a[mt][0], a[mt][1], a[mt][2], a[mt][3], b0, b1);
            }
        }
        __syncthreads();
    }
    #pragma unroll
    for (int mt = 0; mt < 2; mt++) {
        #pragma unroll
        for (int nt = 0; nt < 4; nt++) {
            int col = n0 + nw + nt*8 + 2*ti;
            int r0 = m0 + mw + mt*16 + g, r1 = r0 + 8;
            float2 bi = *(const float2*)&bias[col];
            if (EPI == 1) {
                unsigned* C = (unsigned*)Cv;
                int N2 = N >> 1;
                C[r0*N2 + (col >> 1)] = pack_bf16(fmaxf(c[mt][nt][0] + bi.x, 0.f),
                                                  fmaxf(c[mt][nt][1] + bi.y, 0.f));
                C[r1*N2 + (col >> 1)] = pack_bf16(fmaxf(c[mt][nt][2] + bi.x, 0.f),
                                                  fmaxf(c[mt][nt][3] + bi.y, 0.f));
            } else {
                float* C = (float*)Cv;
                float2 r0v = *(const float2*)&res[r0*N + col];
                float2 r1v = *(const float2*)&res[r1*N + col];
                *(float2*)&C[r0*N + col] = make_float2(c[mt][nt][0] + bi.x + r0v.x,
                                                       c[mt][nt][1] + bi.y + r0v.y);
                *(float2*)&C[r1*N + col] = make_float2(c[mt][nt][2] + bi.x + r1v.x,
                                                       c[mt][nt][3] + bi.y + r1v.y);
            }
        }
    }
}

// ---------------- launcher ----------------
extern "C" void kernel_launch(void* const* d_in, const int* in_sizes, int n_in,
                              void* d_out, int out_size) {
    const float* src     = (const float*)d_in[0];
    const float* norm1_g = (const float*)d_in[1];
    const float* norm1_b = (const float*)d_in[2];
    const float* wq      = (const float*)d_in[3];
    const float* wdw     = (const float*)d_in[4];
    const float* bdw     = (const float*)d_in[5];
    const float* woff    = (const float*)d_in[6];
    const float* wk      = (const float*)d_in[7];
    const float* wv      = (const float*)d_in[8];
    const float* cpb_w0  = (const float*)d_in[9];
    const float* cpb_b0  = (const float*)d_in[10];
    const float* cpb_w1  = (const float*)d_in[11];
    const float* cpb_b1  = (const float*)d_in[12];
    const float* cpb_w2  = (const float*)d_in[13];
    const float* cpb_b2  = (const float*)d_in[14];
    const float* wout    = (const float*)d_in[15];
    const float* bout    = (const float*)d_in[16];
    const float* norm2_g = (const float*)d_in[17];
    const float* norm2_b = (const float*)d_in[18];
    const float* ffn_w1  = (const float*)d_in[19];
    const float* ffn_b1  = (const float*)d_in[20];
    const float* ffn_w2  = (const float*)d_in[21];
    const float* ffn_b2  = (const float*)d_in[22];

    void *p_attn, *p_srcp, *p_src2, *p_ffnh, *p_wp;
    cudaGetSymbolAddress(&p_attn, g_attn);
    cudaGetSymbolAddress(&p_srcp, g_srcp);
    cudaGetSymbolAddress(&p_src2, g_src2);
    cudaGetSymbolAddress(&p_ffnh, g_ffnh);
    cudaGetSymbolAddress(&p_wp,   g_wp);
    unsigned* wp = (unsigned*)p_wp;

    pack_ln_kernel<<<648, 256>>>(wout, ffn_w1, ffn_w2, cpb_w1, wp, src, norm1_g, norm1_b);
    qproj_kernel<<<dim3(16, 8), 256>>>(wq);
    conv_kernel<<<dim3(16, 16), 128>>>(wdw, bdw);
    offsets_cpbf_kernel<<<dim3(16, 4), 256>>>(woff);
    sample_kv_kernel<<<dim3(16, 4), 256>>>(wk, wv);
    attn_kernel<<<dim3(32, 16), 256>>>(cpb_w0, cpb_b0, cpb_b1, cpb_w2, cpb_b2);
    gemm_bf16<64, 0><<<dim3(4, 32), 128>>>((const unsigned*)p_attn, wp, bout, src,
                                           p_srcp, 2048, 256, 128);
    ln2_kernel<<<256, 256>>>((const float*)p_srcp, norm2_g, norm2_b, (unsigned*)p_src2);
    gemm_bf16<128, 1><<<dim3(16, 16), 256>>>((const unsigned*)p_src2, wp + 32768, ffn_b1,
                                             nullptr, p_ffnh, 2048, 1024, 128);
    gemm_bf16<64, 0><<<dim3(4, 32), 128>>>((const unsigned*)p_ffnh, wp + 163840, ffn_b2,
                                           (const float*)p_srcp, d_out, 2048, 256, 512);
}